// round 1
// baseline (speedup 1.0000x reference)
#include <cuda_runtime.h>
#include <cstdint>
#include <math_constants.h>

#define B_DIM 4
#define T_DIM 4096
#define C_DIM 512
#define ATTN_SCALE 0.044194173824159216f  // 1/sqrt(512)

// Scratch for projected Q/K/V (fp32). __device__ globals per allocation rules.
__device__ float g_Qp[B_DIM * T_DIM * C_DIM];
__device__ float g_Kp[B_DIM * T_DIM * C_DIM];
__device__ float g_Vp[B_DIM * T_DIM * C_DIM];

__device__ __forceinline__ uint32_t f2tf(float x) {
    uint32_t u;
    asm("cvt.rna.tf32.f32 %0, %1;" : "=r"(u) : "f"(x));
    return u;
}

__device__ __forceinline__ void cp16(void* s, const void* g) {
    uint32_t sa = (uint32_t)__cvta_generic_to_shared(s);
    asm volatile("cp.async.cg.shared.global [%0], [%1], 16;" :: "r"(sa), "l"(g));
}
#define CP_COMMIT asm volatile("cp.async.commit_group;")
#define CP_WAIT(N) asm volatile("cp.async.wait_group %0;" :: "n"(N))

#define MMA_TF32(d, a0, a1, a2, a3, b0, b1)                                  \
    asm volatile(                                                            \
        "mma.sync.aligned.m16n8k8.row.col.f32.tf32.tf32.f32 "                \
        "{%0,%1,%2,%3},{%4,%5,%6,%7},{%8,%9},{%0,%1,%2,%3};"                 \
        : "+f"((d)[0]), "+f"((d)[1]), "+f"((d)[2]), "+f"((d)[3])             \
        : "r"(a0), "r"(a1), "r"(a2), "r"(a3), "r"(b0), "r"(b1))

// ============================================================================
// Projection GEMM: out[M,N] = x[M,K] @ W[K,N] + b,  M=16384, K=N=512
// z dim selects q/k/v. BM=128, BN=64, BK=16, 256 threads (warps 4x2).
// ============================================================================
__global__ __launch_bounds__(256) void proj_kernel(
    const float* __restrict__ xq, const float* __restrict__ xk, const float* __restrict__ xv,
    const float* __restrict__ Wq, const float* __restrict__ bq,
    const float* __restrict__ Wk, const float* __restrict__ bk,
    const float* __restrict__ Wv, const float* __restrict__ bv)
{
    __shared__ float As[2][128][20];  // pad 16->20 (conflict-free A frags)
    __shared__ float Bs[2][16][68];

    const int which = blockIdx.z;
    const float* x    = (which == 0) ? xq : (which == 1) ? xk : xv;
    const float* W    = (which == 0) ? Wq : (which == 1) ? Wk : Wv;
    const float* bias = (which == 0) ? bq : (which == 1) ? bk : bv;
    float* out        = (which == 0) ? g_Qp : (which == 1) ? g_Kp : g_Vp;

    const int m0 = blockIdx.x * 128;
    const int n0 = blockIdx.y * 64;
    const int tid = threadIdx.x, lane = tid & 31, wid = tid >> 5;
    const int wr = wid >> 1, wc = wid & 1;   // 4 x 2 warp grid

    float acc[2][4][4];
#pragma unroll
    for (int a = 0; a < 2; a++)
#pragma unroll
        for (int b = 0; b < 4; b++)
#pragma unroll
            for (int c = 0; c < 4; c++) acc[a][b][c] = 0.f;

    auto issue = [&](int buf, int k0) {
#pragma unroll
        for (int j = 0; j < 2; j++) {
            int i = tid + 256 * j;
            int row = i >> 2, cf = i & 3;
            cp16(&As[buf][row][cf * 4], x + (size_t)(m0 + row) * C_DIM + k0 + cf * 4);
        }
        {
            int row = tid >> 4, cf = tid & 15;
            cp16(&Bs[buf][row][cf * 4], W + (size_t)(k0 + row) * C_DIM + n0 + cf * 4);
        }
        CP_COMMIT;
    };

    issue(0, 0);
    for (int kt = 0; kt < 32; ++kt) {
        if (kt + 1 < 32) { issue((kt + 1) & 1, (kt + 1) * 16); CP_WAIT(1); }
        else             { CP_WAIT(0); }
        __syncthreads();
        const int buf = kt & 1;
#pragma unroll
        for (int ks = 0; ks < 2; ++ks) {
            uint32_t afr[2][4];
#pragma unroll
            for (int mt = 0; mt < 2; ++mt) {
                int r = wr * 32 + mt * 16 + (lane >> 2);
                int cc = ks * 8 + (lane & 3);
                afr[mt][0] = f2tf(As[buf][r][cc]);
                afr[mt][1] = f2tf(As[buf][r + 8][cc]);
                afr[mt][2] = f2tf(As[buf][r][cc + 4]);
                afr[mt][3] = f2tf(As[buf][r + 8][cc + 4]);
            }
#pragma unroll
            for (int nt = 0; nt < 4; ++nt) {
                int n = wc * 32 + nt * 8 + (lane >> 2);
                int kk = ks * 8 + (lane & 3);
                uint32_t b0 = f2tf(Bs[buf][kk][n]);
                uint32_t b1 = f2tf(Bs[buf][kk + 4][n]);
                MMA_TF32(acc[0][nt], afr[0][0], afr[0][1], afr[0][2], afr[0][3], b0, b1);
                MMA_TF32(acc[1][nt], afr[1][0], afr[1][1], afr[1][2], afr[1][3], b0, b1);
            }
        }
        __syncthreads();
    }

#pragma unroll
    for (int mt = 0; mt < 2; ++mt) {
        int row = m0 + wr * 32 + mt * 16 + (lane >> 2);
#pragma unroll
        for (int nt = 0; nt < 4; ++nt) {
            int col = n0 + wc * 32 + nt * 8 + 2 * (lane & 3);
            float2 bb = *(const float2*)&bias[col];
            float2 v0 = make_float2(acc[mt][nt][0] + bb.x, acc[mt][nt][1] + bb.y);
            float2 v1 = make_float2(acc[mt][nt][2] + bb.x, acc[mt][nt][3] + bb.y);
            *(float2*)&out[(size_t)row * C_DIM + col] = v0;
            *(float2*)&out[(size_t)(row + 8) * C_DIM + col] = v1;
        }
    }
}

// ============================================================================
// Flash attention, H=1, d=512. BM=BN=64. Q tile resident in smem (fp32),
// K/V streamed in 64-wide d-chunks (cp.async double buffer). O in registers.
// 256 threads, warps 4(rows) x 2(cols). One CTA per (batch, query-tile).
// ============================================================================
#define QS_STRIDE 516
#define KV_STRIDE 68
#define SMEM_FLOATS (64 * QS_STRIDE + 2 * 64 * KV_STRIDE + 64 * KV_STRIDE + 3 * 64)

__global__ __launch_bounds__(256, 1) void attn_kernel(float* __restrict__ out)
{
    extern __shared__ float sm[];
    float* Qs     = sm;                                  // [64][516]
    float* KVb    = sm + 64 * QS_STRIDE;                 // [2][64][68]
    float* Ps     = KVb + 2 * 64 * KV_STRIDE;            // [64][68]
    float* row_m  = Ps + 64 * KV_STRIDE;                 // [64]
    float* row_l  = row_m + 64;                          // [64]
    float* row_al = row_l + 64;                          // [64]

    const int bid = blockIdx.x;
    const int b = bid >> 6;
    const int j = bid & 63;
    const int qt = (j & 1) ? (j >> 1) : (63 - (j >> 1));  // zig-zag load balance

    const float* Qg = g_Qp + ((size_t)b * T_DIM + (size_t)qt * 64) * C_DIM;
    const float* Kg = g_Kp + (size_t)b * T_DIM * C_DIM;
    const float* Vg = g_Vp + (size_t)b * T_DIM * C_DIM;

    const int tid = threadIdx.x, lane = tid & 31, wid = tid >> 5;
    const int wr = wid >> 1, wc = wid & 1;

    // Q tile: 64 x 512 fp32
    for (int i = tid; i < 64 * 128; i += 256) {
        int row = i >> 7, cf = i & 127;
        cp16(&Qs[row * QS_STRIDE + cf * 4], Qg + (size_t)row * C_DIM + cf * 4);
    }
    CP_COMMIT;
    if (tid < 64) { row_m[tid] = -CUDART_INF_F; row_l[tid] = 0.f; }

    float o[8][4][4];
#pragma unroll
    for (int c = 0; c < 8; c++)
#pragma unroll
        for (int n = 0; n < 4; n++)
#pragma unroll
            for (int e = 0; e < 4; e++) o[c][n][e] = 0.f;

    CP_WAIT(0);
    __syncthreads();

    auto issueKV = [&](int buf, const float* base, int c) {
        float* dst = KVb + buf * 64 * KV_STRIDE;
        for (int i = tid; i < 64 * 16; i += 256) {
            int row = i >> 4, cf = i & 15;
            cp16(&dst[row * KV_STRIDE + cf * 4], base + (size_t)row * C_DIM + c * 64 + cf * 4);
        }
        CP_COMMIT;
    };

    const int nkt = qt + 1;
    for (int kt = 0; kt < nkt; ++kt) {
        const float* Kt = Kg + (size_t)kt * 64 * C_DIM;
        const float* Vt = Vg + (size_t)kt * 64 * C_DIM;

        // ---------------- S = Q K^T (accumulate over 8 d-chunks) ----------------
        float sacc[4][4];
#pragma unroll
        for (int n = 0; n < 4; n++)
#pragma unroll
            for (int e = 0; e < 4; e++) sacc[n][e] = 0.f;

        issueKV(0, Kt, 0);
        for (int c = 0; c < 8; ++c) {
            if (c + 1 < 8) { issueKV((c + 1) & 1, Kt, c + 1); CP_WAIT(1); }
            else           { CP_WAIT(0); }
            __syncthreads();
            const float* kb = KVb + (c & 1) * 64 * KV_STRIDE;
#pragma unroll
            for (int ks = 0; ks < 8; ++ks) {
                int r0 = wr * 16 + (lane >> 2);
                int qc = c * 64 + ks * 8 + (lane & 3);
                uint32_t a0 = f2tf(Qs[r0 * QS_STRIDE + qc]);
                uint32_t a1 = f2tf(Qs[(r0 + 8) * QS_STRIDE + qc]);
                uint32_t a2 = f2tf(Qs[r0 * QS_STRIDE + qc + 4]);
                uint32_t a3 = f2tf(Qs[(r0 + 8) * QS_STRIDE + qc + 4]);
#pragma unroll
                for (int nt = 0; nt < 4; ++nt) {
                    int n = wc * 32 + nt * 8 + (lane >> 2);
                    int kk = ks * 8 + (lane & 3);
                    uint32_t b0 = f2tf(kb[n * KV_STRIDE + kk]);
                    uint32_t b1 = f2tf(kb[n * KV_STRIDE + kk + 4]);
                    MMA_TF32(sacc[nt], a0, a1, a2, a3, b0, b1);
                }
            }
            __syncthreads();
        }

        // ---------------- mask (diagonal tile only) + store S ----------------
        const bool diag = (kt == qt);
        {
            int r0 = wr * 16 + (lane >> 2);
#pragma unroll
            for (int nt = 0; nt < 4; ++nt) {
                int c0 = wc * 32 + nt * 8 + 2 * (lane & 3);
                float s0 = sacc[nt][0], s1 = sacc[nt][1], s2 = sacc[nt][2], s3 = sacc[nt][3];
                if (diag) {
                    if (c0     > r0)     s0 = -1e30f;
                    if (c0 + 1 > r0)     s1 = -1e30f;
                    if (c0     > r0 + 8) s2 = -1e30f;
                    if (c0 + 1 > r0 + 8) s3 = -1e30f;
                }
                *(float2*)&Ps[r0 * KV_STRIDE + c0]       = make_float2(s0, s1);
                *(float2*)&Ps[(r0 + 8) * KV_STRIDE + c0] = make_float2(s2, s3);
            }
        }
        __syncthreads();

        issueKV(0, Vt, 0);  // prefetch V chunk 0, overlapped with softmax

        // ---------------- online softmax (thread t: row t>>2, 16 cols) ----------------
        {
            int row = tid >> 2, seg = tid & 3;
            float* pr = Ps + row * KV_STRIDE + seg * 16;
            float vloc[16];
            float mx = -CUDART_INF_F;
#pragma unroll
            for (int i = 0; i < 16; i++) { vloc[i] = pr[i] * ATTN_SCALE; mx = fmaxf(mx, vloc[i]); }
            mx = fmaxf(mx, __shfl_xor_sync(0xffffffffu, mx, 1));
            mx = fmaxf(mx, __shfl_xor_sync(0xffffffffu, mx, 2));
            float mold = row_m[row];
            float mnew = fmaxf(mold, mx);
            float sum = 0.f;
#pragma unroll
            for (int i = 0; i < 16; i++) { float p = __expf(vloc[i] - mnew); pr[i] = p; sum += p; }
            sum += __shfl_xor_sync(0xffffffffu, sum, 1);
            sum += __shfl_xor_sync(0xffffffffu, sum, 2);
            if (seg == 0) {
                float alpha = __expf(mold - mnew);
                row_al[row] = alpha;
                row_l[row] = row_l[row] * alpha + sum;
                row_m[row] = mnew;
            }
        }
        __syncthreads();

        // ---------------- rescale O, cache P fragments ----------------
        {
            int r0 = wr * 16 + (lane >> 2);
            float al0 = row_al[r0], al1 = row_al[r0 + 8];
#pragma unroll
            for (int c = 0; c < 8; c++)
#pragma unroll
                for (int nt = 0; nt < 4; nt++) {
                    o[c][nt][0] *= al0; o[c][nt][1] *= al0;
                    o[c][nt][2] *= al1; o[c][nt][3] *= al1;
                }
        }
        uint32_t pa[8][4];
        {
            int r0 = wr * 16 + (lane >> 2);
#pragma unroll
            for (int ks = 0; ks < 8; ks++) {
                int kk = ks * 8 + (lane & 3);
                pa[ks][0] = f2tf(Ps[r0 * KV_STRIDE + kk]);
                pa[ks][1] = f2tf(Ps[(r0 + 8) * KV_STRIDE + kk]);
                pa[ks][2] = f2tf(Ps[r0 * KV_STRIDE + kk + 4]);
                pa[ks][3] = f2tf(Ps[(r0 + 8) * KV_STRIDE + kk + 4]);
            }
        }

        // ---------------- O += P V (8 d-chunks) ----------------
#pragma unroll
        for (int c = 0; c < 8; ++c) {
            if (c + 1 < 8) { issueKV((c + 1) & 1, Vt, c + 1); CP_WAIT(1); }
            else           { CP_WAIT(0); }
            __syncthreads();
            const float* vb = KVb + (c & 1) * 64 * KV_STRIDE;
#pragma unroll
            for (int ks = 0; ks < 8; ++ks) {
#pragma unroll
                for (int nt = 0; nt < 4; ++nt) {
                    int n = wc * 32 + nt * 8 + (lane >> 2);
                    int kk = ks * 8 + (lane & 3);
                    uint32_t b0 = f2tf(vb[kk * KV_STRIDE + n]);
                    uint32_t b1 = f2tf(vb[(kk + 4) * KV_STRIDE + n]);
                    MMA_TF32(o[c][nt], pa[ks][0], pa[ks][1], pa[ks][2], pa[ks][3], b0, b1);
                }
            }
            __syncthreads();
        }
    }

    // ---------------- epilogue: O / l -> out ----------------
    {
        int r0 = wr * 16 + (lane >> 2);
        float inv0 = 1.f / row_l[r0];
        float inv1 = 1.f / row_l[r0 + 8];
        float* og = out + ((size_t)b * T_DIM + (size_t)qt * 64) * C_DIM;
#pragma unroll
        for (int c = 0; c < 8; c++) {
#pragma unroll
            for (int nt = 0; nt < 4; nt++) {
                int col = c * 64 + wc * 32 + nt * 8 + 2 * (lane & 3);
                *(float2*)&og[(size_t)r0 * C_DIM + col] =
                    make_float2(o[c][nt][0] * inv0, o[c][nt][1] * inv0);
                *(float2*)&og[(size_t)(r0 + 8) * C_DIM + col] =
                    make_float2(o[c][nt][2] * inv1, o[c][nt][3] * inv1);
            }
        }
    }
}

// ============================================================================
// Launch
// ============================================================================
extern "C" void kernel_launch(void* const* d_in, const int* in_sizes, int n_in,
                              void* d_out, int out_size)
{
    const float* q  = (const float*)d_in[0];
    const float* k  = (const float*)d_in[1];
    const float* v  = (const float*)d_in[2];
    const float* Wq = (const float*)d_in[3];
    const float* bq = (const float*)d_in[4];
    const float* Wk = (const float*)d_in[5];
    const float* bk = (const float*)d_in[6];
    const float* Wv = (const float*)d_in[7];
    const float* bv = (const float*)d_in[8];
    float* out = (float*)d_out;

    cudaFuncSetAttribute(attn_kernel, cudaFuncAttributeMaxDynamicSharedMemorySize,
                         SMEM_FLOATS * (int)sizeof(float));

    dim3 pgrid(16384 / 128, 512 / 64, 3);
    proj_kernel<<<pgrid, 256>>>(q, k, v, Wq, bq, Wk, bk, Wv, bv);

    attn_kernel<<<B_DIM * (T_DIM / 64), 256, SMEM_FLOATS * (int)sizeof(float)>>>(out);
}